// round 14
// baseline (speedup 1.0000x reference)
#include <cuda_runtime.h>

// Round 12: R9 engine (4 producer + 4 consumer warps, 256 thr, 2 blocks/SM)
// with the tile-lockstep __syncthreads replaced by a 3-deep buffer ring and
// named-barrier handshakes. Producers stream the HBM data continuously,
// up to 2 tiles ahead of the GEMM consumers.
//
//   FULL_b  (ids 1..3): producers bar.arrive after writing buffer b,
//                       consumers bar.sync before reading it.
//   EMPTY_b (ids 4..6): consumers bar.arrive after reading buffer b,
//                       producers bar.sync before overwriting it (skip first lap).

#define N_NODES 50000
#define S_NEIGH 25
#define DIM     128
#define OUTD    128
#define KDIM    256
#define TM      32
#define THREADS 256
#define A_STRIDE 260                 // floats per tile row (pad, 16B-aligned)
#define TILE_FLOATS (TM * A_STRIDE)  // 8320
#define NBUF    3
#define NT      3125                 // 2*N_NODES / TM
#define GRID    296                  // 2 persistent blocks per SM
#define SMEM_BYTES (NBUF * TILE_FLOATS * 4)   // 99840

typedef unsigned long long u64;

// ---- packed f32x2 helpers ----
__device__ __forceinline__ u64 fadd2(u64 a, u64 b) {
    u64 d; asm("add.rn.f32x2 %0, %1, %2;" : "=l"(d) : "l"(a), "l"(b)); return d;
}
__device__ __forceinline__ u64 fmul2(u64 a, u64 b) {
    u64 d; asm("mul.rn.f32x2 %0, %1, %2;" : "=l"(d) : "l"(a), "l"(b)); return d;
}
__device__ __forceinline__ u64 ffma2(u64 a, u64 b, u64 c) {
    u64 d; asm("fma.rn.f32x2 %0, %1, %2, %3;" : "=l"(d) : "l"(a), "l"(b), "l"(c)); return d;
}
__device__ __forceinline__ u64 bcast2(float x) {          // {x, x}
    u64 d; asm("mov.b64 %0, {%1, %1};" : "=l"(d) : "f"(x)); return d;
}
// 16B streaming load, evict-first, NON-volatile so ptxas can batch for MLP.
__device__ __forceinline__ ulonglong2 ldcs16(const float* p) {
    ulonglong2 v;
    asm("ld.global.cs.v2.u64 {%0, %1}, [%2];" : "=l"(v.x), "=l"(v.y) : "l"(p));
    return v;
}
__device__ __forceinline__ float4 ld4(const float* p) {
    return *reinterpret_cast<const float4*>(p);
}
// ---- named barriers ----
__device__ __forceinline__ void nbar_sync(int id, int cnt) {
    asm volatile("bar.sync %0, %1;" :: "r"(id), "r"(cnt) : "memory");
}
__device__ __forceinline__ void nbar_arrive(int id, int cnt) {
    asm volatile("bar.arrive %0, %1;" :: "r"(id), "r"(cnt) : "memory");
}

// ---- producer: build cat tile rows [x | mean(neg)], 2 interleaved items ----
__device__ __forceinline__ void produce_tile(
    float* __restrict__ Adst, int tile,
    const float* __restrict__ src, const float* __restrict__ src_neg,
    const float* __restrict__ dst, const float* __restrict__ dst_neg,
    int ptid, u64 inv2)
{
    const long t0 = (long)tile * TM;
    // 1024 items; ptid in [0,128): items {i, i+128} for i = ptid, ptid+256, ...
    for (int i = ptid; i < TM * (DIM / 4); i += 256) {
        const int ia = i;
        const int ib = i + 128;

        const int ra = ia >> 5, d4a = (ia & 31) << 2;
        const int rb = ib >> 5, d4b = (ib & 31) << 2;

        const float *xpa, *npa, *xpb, *npb;
        {
            const long task = t0 + ra;
            if (task < N_NODES) { xpa = src + task * DIM; npa = src_neg + task * (long)(S_NEIGH * DIM); }
            else { const long rr = task - N_NODES; xpa = dst + rr * DIM; npa = dst_neg + rr * (long)(S_NEIGH * DIM); }
        }
        {
            const long task = t0 + rb;
            if (task < N_NODES) { xpb = src + task * DIM; npb = src_neg + task * (long)(S_NEIGH * DIM); }
            else { const long rr = task - N_NODES; xpb = dst + rr * DIM; npb = dst_neg + rr * (long)(S_NEIGH * DIM); }
        }

        const float* pa = npa + d4a;
        const float* pb = npb + d4b;

        u64 sa0 = 0ull, sa1 = 0ull, sb0 = 0ull, sb1 = 0ull;
        #pragma unroll
        for (int j = 0; j < S_NEIGH; j++) {
            const ulonglong2 va = ldcs16(pa + j * DIM);
            const ulonglong2 vb = ldcs16(pb + j * DIM);
            sa0 = fadd2(sa0, va.x); sa1 = fadd2(sa1, va.y);
            sb0 = fadd2(sb0, vb.x); sb1 = fadd2(sb1, vb.y);
        }

        const ulonglong2 xva = *reinterpret_cast<const ulonglong2*>(xpa + d4a);
        const ulonglong2 xvb = *reinterpret_cast<const ulonglong2*>(xpb + d4b);

        ulonglong2 ma, mb;
        ma.x = fmul2(sa0, inv2); ma.y = fmul2(sa1, inv2);
        mb.x = fmul2(sb0, inv2); mb.y = fmul2(sb1, inv2);

        *reinterpret_cast<ulonglong2*>(Adst + ra * A_STRIDE + d4a)       = xva;
        *reinterpret_cast<ulonglong2*>(Adst + ra * A_STRIDE + DIM + d4a) = ma;
        *reinterpret_cast<ulonglong2*>(Adst + rb * A_STRIDE + d4b)       = xvb;
        *reinterpret_cast<ulonglong2*>(Adst + rb * A_STRIDE + DIM + d4b) = mb;
    }
}

__global__ __launch_bounds__(THREADS, 2)
void magg_kernel(const float* __restrict__ src,
                 const float* __restrict__ src_neg,
                 const float* __restrict__ dst,
                 const float* __restrict__ dst_neg,
                 const float* __restrict__ w,
                 float* __restrict__ out)
{
    extern __shared__ float A[];     // NBUF buffers of TILE_FLOATS

    const int tid  = threadIdx.x;
    const int wid  = tid >> 5;
    const int lane = tid & 31;

    u64 inv2; asm("mov.b64 %0, {%1, %1};" : "=l"(inv2) : "f"(1.0f / (float)S_NEIGH));

    if (wid < 4) {
        // ================= producers =================
        int b = 0, i = 0;
        for (int t = blockIdx.x; t < NT; t += GRID, i++) {
            if (i >= NBUF) nbar_sync(4 + b, 2 * THREADS / 2);        // EMPTY_b (256)
            produce_tile(A + b * TILE_FLOATS, t, src, src_neg, dst, dst_neg,
                         tid, inv2);
            __threadfence_block();                                   // STS visible
            nbar_arrive(1 + b, 256);                                 // FULL_b
            if (++b == NBUF) b = 0;
        }
    } else {
        // ================= consumers =================
        // warp cw: rows 8cw..8cw+7; lane: cols 4*lane..4*lane+3 (2 f32x2 pairs)
        const int cw = wid - 4;
        const int r0 = cw << 3;
        const int c0 = lane << 2;

        int b = 0;
        for (int t = blockIdx.x; t < NT; t += GRID) {
            nbar_sync(1 + b, 256);                                   // FULL_b
            const float* Ab = A + b * TILE_FLOATS;

            u64 acc[8][2];
            #pragma unroll
            for (int j = 0; j < 8; j++) { acc[j][0] = 0ull; acc[j][1] = 0ull; }

            #pragma unroll 4
            for (int k4 = 0; k4 < KDIM / 4; k4++) {
                float4 a[8];
                #pragma unroll
                for (int j = 0; j < 8; j++)
                    a[j] = ld4(Ab + (r0 + j) * A_STRIDE + (k4 << 2));  // broadcast LDS.128

                #pragma unroll
                for (int kk = 0; kk < 4; kk++) {
                    const float4 wv = ld4(w + (long)((k4 << 2) + kk) * OUTD + c0);
                    const u64 wp0 = reinterpret_cast<const u64*>(&wv)[0];
                    const u64 wp1 = reinterpret_cast<const u64*>(&wv)[1];
                    #pragma unroll
                    for (int j = 0; j < 8; j++) {
                        const u64 ap = bcast2((&a[j].x)[kk]);   // ALU-pipe pack
                        acc[j][0] = ffma2(ap, wp0, acc[j][0]);
                        acc[j][1] = ffma2(ap, wp1, acc[j][1]);
                    }
                }
            }
            // all LDS values consumed by FFMAs (in-order issue) -> safe to release
            nbar_arrive(4 + b, 256);                                 // EMPTY_b

            const long row0 = (long)t * TM + r0;
            float* o = out + row0 * OUTD + c0;
            #pragma unroll
            for (int j = 0; j < 8; j++) {
                ulonglong2 r; r.x = acc[j][0]; r.y = acc[j][1];
                *reinterpret_cast<ulonglong2*>(o + (long)j * OUTD) = r;
            }
            if (++b == NBUF) b = 0;
        }
    }
}

extern "C" void kernel_launch(void* const* d_in, const int* in_sizes, int n_in,
                              void* d_out, int out_size)
{
    const float* src     = (const float*)d_in[0];
    const float* src_neg = (const float*)d_in[1];
    const float* dst     = (const float*)d_in[2];
    const float* dst_neg = (const float*)d_in[3];
    const float* w       = (const float*)d_in[4];
    float* out = (float*)d_out;

    cudaFuncSetAttribute(magg_kernel, cudaFuncAttributeMaxDynamicSharedMemorySize,
                         SMEM_BYTES);
    magg_kernel<<<GRID, THREADS, SMEM_BYTES>>>(src, src_neg, dst, dst_neg, w, out);
}

// round 15
// speedup vs baseline: 1.4986x; 1.4986x over previous
#include <cuda_runtime.h>

// Round 15: R9 engine (best: 227.9us) + register-free MLP via L2 prefetch.
//   4 producer + 4 consumer warps, 256 thr, 2 blocks/SM, double-buffered cat
//   tile, one __syncthreads per tile (the only structure that has worked).
// NEW: while reducing item-pair i, lanes {0,8,16,24} prefetch.global.L2 the
//      next pair's 50 cache lines -> next iteration's ld.cs hit L2.
// NEW: out stores use st.global.cs (write-streaming, no L2 pollution).

#define N_NODES 50000
#define S_NEIGH 25
#define DIM     128
#define OUTD    128
#define KDIM    256
#define TM      32
#define THREADS 256
#define A_STRIDE 260            // floats per tile row (pad, 16B-aligned)
#define NT      3125            // 2*N_NODES / TM
#define GRID    296             // 2 persistent blocks per SM

typedef unsigned long long u64;

// ---- packed f32x2 helpers ----
__device__ __forceinline__ u64 fadd2(u64 a, u64 b) {
    u64 d; asm("add.rn.f32x2 %0, %1, %2;" : "=l"(d) : "l"(a), "l"(b)); return d;
}
__device__ __forceinline__ u64 fmul2(u64 a, u64 b) {
    u64 d; asm("mul.rn.f32x2 %0, %1, %2;" : "=l"(d) : "l"(a), "l"(b)); return d;
}
__device__ __forceinline__ u64 ffma2(u64 a, u64 b, u64 c) {
    u64 d; asm("fma.rn.f32x2 %0, %1, %2, %3;" : "=l"(d) : "l"(a), "l"(b), "l"(c)); return d;
}
__device__ __forceinline__ u64 bcast2(float x) {          // {x, x}
    u64 d; asm("mov.b64 %0, {%1, %1};" : "=l"(d) : "f"(x)); return d;
}
// 16B streaming load, evict-first, NON-volatile so ptxas can batch for MLP.
__device__ __forceinline__ ulonglong2 ldcs16(const float* p) {
    ulonglong2 v;
    asm("ld.global.cs.v2.u64 {%0, %1}, [%2];" : "=l"(v.x), "=l"(v.y) : "l"(p));
    return v;
}
// 16B streaming store (evict-first; out is never re-read)
__device__ __forceinline__ void stcs16(float* p, u64 a, u64 b) {
    asm volatile("st.global.cs.v2.u64 [%0], {%1, %2};" :: "l"(p), "l"(a), "l"(b) : "memory");
}
// L2 prefetch: no destination register, no scoreboard -> free MLP
__device__ __forceinline__ void pf_l2(const float* p) {
    asm volatile("prefetch.global.L2 [%0];" :: "l"(p));
}
__device__ __forceinline__ float4 ld4(const float* p) {
    return *reinterpret_cast<const float4*>(p);
}

// ---- producer: build cat tile rows [x | mean(neg)], 2 interleaved items,
//      prefetching the NEXT pair's lines into L2 while reducing this one ----
__device__ __forceinline__ void produce_tile(
    float* __restrict__ Adst, int tile,
    const float* __restrict__ src, const float* __restrict__ src_neg,
    const float* __restrict__ dst, const float* __restrict__ dst_neg,
    int ptid, int pthreads, u64 inv2)
{
    const long t0 = (long)tile * TM;
    const int  lane = ptid & 31;
    const bool pfl  = ((lane & 7) == 0);     // 4 lanes cover the warp's 512B/row

    for (int i = ptid; i < TM * (DIM / 4); i += 2 * pthreads) {
        const int ia = i;
        const int ib = i + pthreads;

        const int ra = ia >> 5, d4a = (ia & 31) << 2;
        const int rb = ib >> 5, d4b = (ib & 31) << 2;

        const float *xpa, *npa, *xpb, *npb;
        {
            const long task = t0 + ra;
            if (task < N_NODES) { xpa = src + task * DIM; npa = src_neg + task * (long)(S_NEIGH * DIM); }
            else { const long rr = task - N_NODES; xpa = dst + rr * DIM; npa = dst_neg + rr * (long)(S_NEIGH * DIM); }
        }
        {
            const long task = t0 + rb;
            if (task < N_NODES) { xpb = src + task * DIM; npb = src_neg + task * (long)(S_NEIGH * DIM); }
            else { const long rr = task - N_NODES; xpb = dst + rr * DIM; npb = dst_neg + rr * (long)(S_NEIGH * DIM); }
        }

        // ---- next-pair prefetch pointers (valid whenever in_ < item count) ----
        const int in_ = i + 2 * pthreads;
        const float* qa = 0; const float* qb = 0;
        if (in_ < TM * (DIM / 4)) {
            const int rna = in_ >> 5,            dna = (in_ & 31) << 2;
            const int inb = in_ + pthreads;
            const int rnb = inb >> 5,            dnb = (inb & 31) << 2;
            {
                const long task = t0 + rna;
                qa = (task < N_NODES) ? src_neg + task * (long)(S_NEIGH * DIM) + dna
                                      : dst_neg + (task - N_NODES) * (long)(S_NEIGH * DIM) + dna;
            }
            {
                const long task = t0 + rnb;
                qb = (task < N_NODES) ? src_neg + task * (long)(S_NEIGH * DIM) + dnb
                                      : dst_neg + (task - N_NODES) * (long)(S_NEIGH * DIM) + dnb;
            }
        }

        const float* pa = npa + d4a;
        const float* pb = npb + d4b;

        u64 sa0 = 0ull, sa1 = 0ull, sb0 = 0ull, sb1 = 0ull;
        #pragma unroll
        for (int j = 0; j < S_NEIGH; j++) {
            const ulonglong2 va = ldcs16(pa + j * DIM);
            const ulonglong2 vb = ldcs16(pb + j * DIM);
            if (pfl && qa) { pf_l2(qa + j * DIM); pf_l2(qb + j * DIM); }
            sa0 = fadd2(sa0, va.x); sa1 = fadd2(sa1, va.y);
            sb0 = fadd2(sb0, vb.x); sb1 = fadd2(sb1, vb.y);
        }

        const ulonglong2 xva = *reinterpret_cast<const ulonglong2*>(xpa + d4a);
        const ulonglong2 xvb = *reinterpret_cast<const ulonglong2*>(xpb + d4b);

        ulonglong2 ma, mb;
        ma.x = fmul2(sa0, inv2); ma.y = fmul2(sa1, inv2);
        mb.x = fmul2(sb0, inv2); mb.y = fmul2(sb1, inv2);

        *reinterpret_cast<ulonglong2*>(Adst + ra * A_STRIDE + d4a)       = xva;
        *reinterpret_cast<ulonglong2*>(Adst + ra * A_STRIDE + DIM + d4a) = ma;
        *reinterpret_cast<ulonglong2*>(Adst + rb * A_STRIDE + d4b)       = xvb;
        *reinterpret_cast<ulonglong2*>(Adst + rb * A_STRIDE + DIM + d4b) = mb;
    }
}

__global__ __launch_bounds__(THREADS, 2)
void magg_kernel(const float* __restrict__ src,
                 const float* __restrict__ src_neg,
                 const float* __restrict__ dst,
                 const float* __restrict__ dst_neg,
                 const float* __restrict__ w,
                 float* __restrict__ out)
{
    __shared__ float A[2][TM][A_STRIDE];   // 66.6 KB double buffer

    const int tid  = threadIdx.x;
    const int wid  = tid >> 5;
    const int lane = tid & 31;

    u64 inv2; asm("mov.b64 %0, {%1, %1};" : "=l"(inv2) : "f"(1.0f / (float)S_NEIGH));

    produce_tile(&A[0][0][0], blockIdx.x, src, src_neg, dst, dst_neg,
                 tid, THREADS, inv2);
    __syncthreads();

    int buf = 0;
    for (int t = blockIdx.x; t < NT; t += GRID) {
        const int nxt = t + GRID;

        if (wid < 4) {
            // -------- producers: build tile t+GRID --------
            if (nxt < NT) {
                produce_tile(&A[buf ^ 1][0][0], nxt, src, src_neg, dst, dst_neg,
                             tid, 128, inv2);
            }
        } else {
            // -------- consumers: column-paired FFMA2 GEMM of tile t --------
            // warp cw: rows 8cw..8cw+7; lane: cols 4*lane..4*lane+3 (2 pairs)
            const int cw = wid - 4;
            const int r0 = cw << 3;
            const int c0 = lane << 2;
            const float* Ab = &A[buf][0][0];

            u64 acc[8][2];
            #pragma unroll
            for (int j = 0; j < 8; j++) { acc[j][0] = 0ull; acc[j][1] = 0ull; }

            #pragma unroll 4
            for (int k4 = 0; k4 < KDIM / 4; k4++) {
                float4 a[8];
                #pragma unroll
                for (int j = 0; j < 8; j++)
                    a[j] = ld4(Ab + (r0 + j) * A_STRIDE + (k4 << 2));  // broadcast LDS.128

                #pragma unroll
                for (int kk = 0; kk < 4; kk++) {
                    const float4 wv = ld4(w + (long)((k4 << 2) + kk) * OUTD + c0);
                    const u64 wp0 = reinterpret_cast<const u64*>(&wv)[0];
                    const u64 wp1 = reinterpret_cast<const u64*>(&wv)[1];
                    #pragma unroll
                    for (int j = 0; j < 8; j++) {
                        const u64 ap = bcast2((&a[j].x)[kk]);   // ALU-pipe pack
                        acc[j][0] = ffma2(ap, wp0, acc[j][0]);
                        acc[j][1] = ffma2(ap, wp1, acc[j][1]);
                    }
                }
            }

            const long row0 = (long)t * TM + r0;
            float* o = out + row0 * OUTD + c0;
            #pragma unroll
            for (int j = 0; j < 8; j++)
                stcs16(o + (long)j * OUTD, acc[j][0], acc[j][1]);
        }

        __syncthreads();
        buf ^= 1;
    }
}

extern "C" void kernel_launch(void* const* d_in, const int* in_sizes, int n_in,
                              void* d_out, int out_size)
{
    const float* src     = (const float*)d_in[0];
    const float* src_neg = (const float*)d_in[1];
    const float* dst     = (const float*)d_in[2];
    const float* dst_neg = (const float*)d_in[3];
    const float* w       = (const float*)d_in[4];
    float* out = (float*)d_out;

    magg_kernel<<<GRID, THREADS>>>(src, src_neg, dst, dst_neg, w, out);
}